// round 11
// baseline (speedup 1.0000x reference)
#include <cuda_runtime.h>
#include <cuda_fp16.h>
#include <cstdint>

#define N_NODES 40000
#define N_EDGES 640000
#define DF      128
#define N_GRAPHS 128

// ======================= scratch (static device globals) ====================
// NOTE: statics are zero-initialized at load. Replay invariants:
//   g_deg   : zeroed by k_scan_wr (after last read)  -> 0 at next replay
//   g_fill  : zeroed by k_pool                        -> 0 at next replay
//   g_outmax: reset to 0 by k_decode (0 <= enc(f) for all f -> atomicMax OK)
__device__ float  g_h0 [(size_t)N_NODES * DF];
__device__ float  g_h1 [(size_t)N_NODES * DF];
__device__ __half g_hhA[(size_t)N_NODES * DF];   // fp16 mirrors (double buffer)
__device__ __half g_hhB[(size_t)N_NODES * DF];
__device__ float  g_WT [3][DF][256];             // [layer][n][k_cat]
__device__ int    g_rowptr[N_NODES + 1];
__device__ int    g_deg [N_NODES];
__device__ int    g_fill[N_NODES];
__device__ int    g_colidx[N_EDGES];
__device__ int    g_bsum[160];
__device__ int    g_boff[160];
__device__ unsigned g_outmax[N_GRAPHS * DF];
__device__ int    g_is64;

// ======================= helpers ===========================================
__device__ __forceinline__ uint32_t f2tf32(float f) {
    uint32_t r;
    asm("cvt.rna.tf32.f32 %0, %1;" : "=r"(r) : "f"(f));
    return r;
}

#define MMA_TF32(d, a, b0, b1)                                                \
    asm volatile("mma.sync.aligned.m16n8k8.row.col.f32.tf32.tf32.f32 "        \
        "{%0,%1,%2,%3}, {%4,%5,%6,%7}, {%8,%9}, {%0,%1,%2,%3};"               \
        : "+f"((d)[0]), "+f"((d)[1]), "+f"((d)[2]), "+f"((d)[3])              \
        : "r"((a)[0]), "r"((a)[1]), "r"((a)[2]), "r"((a)[3]),                 \
          "r"(b0), "r"(b1))

__device__ __forceinline__ unsigned enc_f(float f) {
    unsigned b = __float_as_uint(f);
    return (b & 0x80000000u) ? ~b : (b | 0x80000000u);
}
__device__ __forceinline__ float dec_f(unsigned u) {
    unsigned b = (u & 0x80000000u) ? (u ^ 0x80000000u) : ~u;
    return __uint_as_float(b);
}

// ======================= init: x->fp16, WT transpose, probe+count ==========
// Grid 10000x256 (= 2.56M threads). g_deg is pre-zeroed (static init /
// previous replay's scan_wr), so counting can run in the same kernel.
__global__ void k_init(const int* __restrict__ ew, const float* __restrict__ x,
                       const float* __restrict__ Wrel0, const float* __restrict__ Wroot0,
                       const float* __restrict__ Wrel1, const float* __restrict__ Wroot1,
                       const float* __restrict__ Wrel2, const float* __restrict__ Wroot2) {
    __shared__ int s_any;
    int i = blockIdx.x * blockDim.x + threadIdx.x;

    // x -> half mirror A (exactly 2.56M half2)
    {
        float2 v = *((const float2*)x + i);
        *((__half2*)g_hhA + i) = __floats2half2_rn(v.x, v.y);
    }

    // weight transpose: 3 * 128 * 256 elements
    if (i < 3 * DF * 256) {
        int layer = i / (DF * 256);
        int idx = i % (DF * 256);
        const float* Wrel  = (layer == 0) ? Wrel0  : (layer == 1) ? Wrel1  : Wrel2;
        const float* Wroot = (layer == 0) ? Wroot0 : (layer == 1) ? Wroot1 : Wroot2;
        int n = idx >> 8;
        int k = idx & 255;
        g_WT[layer][n][k] = (k < DF) ? Wrel[k * DF + n] : Wroot[(k - DF) * DF + n];
    }

    // blocks covering the edge range: block-local probe, then count
    if (blockIdx.x * 256 < N_EDGES) {
        if (threadIdx.x == 0) s_any = 0;
        __syncthreads();
        if (ew[2 * threadIdx.x + 1] != 0) atomicOr(&s_any, 1);
        __syncthreads();
        int is64 = s_any ? 0 : 1;
        if (i == 0) g_is64 = is64;           // consumed by fill/pool
        if (i < N_EDGES) {
            int dst = is64 ? ew[2 * (N_EDGES + i)] : ew[N_EDGES + i];
            atomicAdd(&g_deg[dst], 1);
        }
    }
}

// ======================= scan (3 kernels) ==================================
#define SCAN_BLK 157   // ceil(40000/256)

__global__ void k_scan_part() {
    __shared__ int sh[256];
    int t = threadIdx.x;
    int i = blockIdx.x * 256 + t;
    sh[t] = (i < N_NODES) ? g_deg[i] : 0;
    __syncthreads();
    for (int off = 128; off > 0; off >>= 1) {
        if (t < off) sh[t] += sh[t + off];
        __syncthreads();
    }
    if (t == 0) g_bsum[blockIdx.x] = sh[0];
}

__global__ void k_scan_top() {
    __shared__ int sh[256];
    int t = threadIdx.x;
    int v = (t < SCAN_BLK) ? g_bsum[t] : 0;
    sh[t] = v;
    __syncthreads();
    for (int off = 1; off < 256; off <<= 1) {
        int x = (t >= off) ? sh[t - off] : 0;
        __syncthreads();
        sh[t] += x;
        __syncthreads();
    }
    if (t < SCAN_BLK) g_boff[t] = sh[t] - v;   // exclusive
    if (t == 0) g_rowptr[N_NODES] = N_EDGES;
}

// last reader of g_deg -> zeroes it for the next replay
__global__ void k_scan_wr() {
    __shared__ int sh[256];
    int t = threadIdx.x;
    int i = blockIdx.x * 256 + t;
    int v = (i < N_NODES) ? g_deg[i] : 0;
    sh[t] = v;
    __syncthreads();
    for (int off = 1; off < 256; off <<= 1) {
        int x = (t >= off) ? sh[t - off] : 0;
        __syncthreads();
        sh[t] += x;
        __syncthreads();
    }
    if (i < N_NODES) {
        g_rowptr[i] = g_boff[blockIdx.x] + sh[t] - v;
        g_deg[i] = 0;
    }
}

__global__ void k_fill(const int* __restrict__ ew) {
    int e = blockIdx.x * blockDim.x + threadIdx.x;
    if (e >= N_EDGES) return;
    int is64 = g_is64;
    int src = is64 ? ew[2 * e] : ew[e];
    int dst = is64 ? ew[2 * (N_EDGES + e)] : ew[N_EDGES + e];
    int pos = atomicAdd(&g_fill[dst], 1);
    g_colidx[g_rowptr[dst] + pos] = src;
}

// ======================= fused layer: gather + tf32 MMA + epilogue =========
// CTA = 128 output rows. Phase 1: 8 warps gather 16 nodes each from the fp16
// mirror into smem (tf32). Phase 2: K=256 in 8 chunks of 32; A from smem agg
// (k<128) or global fp32 root (k>=128); B from g_WT. Epilogue: +bias, ReLU,
// fp32 store, and fp16 mirror store for the next layer.
#define AGSTR 132   // 132 % 32 == 4 -> conflict-free fragment loads
#define GSTR  36
#define SM_AGG  (128 * AGSTR)              // 16896 words
#define SM_B    (128 * GSTR)               //  4608 words
#define SM_RT   (128 * GSTR)               //  4608 words
#define SM_WORDS (SM_AGG + SM_B + SM_RT)   // 26112 words = 104448 B

__global__ void __launch_bounds__(256) k_layer(
    const float* __restrict__ xext, int root_sel, int out_sel, int layer,
    const float* __restrict__ bias, int do_relu, int hh_rd)
{
    extern __shared__ uint32_t smem[];
    uint32_t* sAgg = smem;
    uint32_t* sB   = smem + SM_AGG;
    uint32_t* sRt  = smem + SM_AGG + SM_B;

    const float* Aroot = (root_sel == 0) ? xext : (root_sel == 1 ? g_h0 : g_h1);
    float* out = (out_sel == 0) ? g_h0 : g_h1;
    const __half* hhin = hh_rd ? g_hhB : g_hhA;
    __half* hhout = hh_rd ? g_hhA : g_hhB;

    int tid = threadIdx.x;
    int wid = tid >> 5;
    int lane = tid & 31;
    int row0 = blockIdx.x * 128;

    // ---- phase 1: gather 16 nodes per warp ----
    for (int nn = 0; nn < 16; nn++) {
        int nloc = wid * 16 + nn;
        int node = row0 + nloc;
        float4 acc = make_float4(0.f, 0.f, 0.f, 0.f);
        if (node < N_NODES) {
            int beg = g_rowptr[node];
            int end = g_rowptr[node + 1];
            int e = beg;
            for (; e + 3 < end; e += 4) {
                int s0 = g_colidx[e + 0];
                int s1 = g_colidx[e + 1];
                int s2 = g_colidx[e + 2];
                int s3 = g_colidx[e + 3];
                uint2 u0 = __ldg((const uint2*)(hhin + (size_t)s0 * DF) + lane);
                uint2 u1 = __ldg((const uint2*)(hhin + (size_t)s1 * DF) + lane);
                uint2 u2 = __ldg((const uint2*)(hhin + (size_t)s2 * DF) + lane);
                uint2 u3 = __ldg((const uint2*)(hhin + (size_t)s3 * DF) + lane);
                float2 a0 = __half22float2(*(__half2*)&u0.x), b0 = __half22float2(*(__half2*)&u0.y);
                float2 a1 = __half22float2(*(__half2*)&u1.x), b1 = __half22float2(*(__half2*)&u1.y);
                float2 a2 = __half22float2(*(__half2*)&u2.x), b2 = __half22float2(*(__half2*)&u2.y);
                float2 a3 = __half22float2(*(__half2*)&u3.x), b3 = __half22float2(*(__half2*)&u3.y);
                acc.x += (a0.x + a1.x) + (a2.x + a3.x);
                acc.y += (a0.y + a1.y) + (a2.y + a3.y);
                acc.z += (b0.x + b1.x) + (b2.x + b3.x);
                acc.w += (b0.y + b1.y) + (b2.y + b3.y);
            }
            for (; e < end; e++) {
                int s0 = g_colidx[e];
                uint2 u0 = __ldg((const uint2*)(hhin + (size_t)s0 * DF) + lane);
                float2 a0 = __half22float2(*(__half2*)&u0.x), b0 = __half22float2(*(__half2*)&u0.y);
                acc.x += a0.x; acc.y += a0.y; acc.z += b0.x; acc.w += b0.y;
            }
        }
        uint4 p;
        p.x = f2tf32(acc.x); p.y = f2tf32(acc.y);
        p.z = f2tf32(acc.z); p.w = f2tf32(acc.w);
        *(uint4*)&sAgg[nloc * AGSTR + lane * 4] = p;
    }
    __syncthreads();

    // ---- phase 2: MMA over K=256 ----
    int wm = wid & 3;
    int wn = wid >> 2;
    int lq = lane >> 2;
    int lr = lane & 3;
    const float* Bsrc = &g_WT[layer][0][0];

    float acc[2][8][4];
    #pragma unroll
    for (int mt = 0; mt < 2; mt++)
        #pragma unroll
        for (int nt = 0; nt < 8; nt++)
            #pragma unroll
            for (int q = 0; q < 4; q++) acc[mt][nt][q] = 0.f;

    for (int c = 0; c < 8; c++) {
        int kbase = c * 32;

        // fill B chunk
        #pragma unroll
        for (int it = 0; it < 4; it++) {
            int idx = it * 256 + tid;
            int n = idx >> 3, c4 = idx & 7;
            float4 v = *(const float4*)(Bsrc + (size_t)n * 256 + kbase + c4 * 4);
            uint4 p;
            p.x = f2tf32(v.x); p.y = f2tf32(v.y);
            p.z = f2tf32(v.z); p.w = f2tf32(v.w);
            *(uint4*)&sB[n * GSTR + c4 * 4] = p;
        }
        // fill root chunk (k >= 128)
        if (kbase >= 128) {
            int acol = kbase - 128;
            #pragma unroll
            for (int it = 0; it < 4; it++) {
                int idx = it * 256 + tid;
                int r = idx >> 3, c4 = idx & 7;
                int grow = row0 + r;
                float4 v = make_float4(0.f, 0.f, 0.f, 0.f);
                if (grow < N_NODES)
                    v = *(const float4*)(Aroot + (size_t)grow * DF + acol + c4 * 4);
                uint4 p;
                p.x = f2tf32(v.x); p.y = f2tf32(v.y);
                p.z = f2tf32(v.z); p.w = f2tf32(v.w);
                *(uint4*)&sRt[r * GSTR + c4 * 4] = p;
            }
        }
        __syncthreads();

        const uint32_t* Abase = (kbase < 128) ? (sAgg + kbase) : sRt;
        int astr = (kbase < 128) ? AGSTR : GSTR;

        #pragma unroll
        for (int ks = 0; ks < 4; ks++) {
            int k0 = ks * 8;
            uint32_t a[2][4];
            #pragma unroll
            for (int mt = 0; mt < 2; mt++) {
                int mrow = wm * 32 + mt * 16;
                a[mt][0] = Abase[(mrow + lq    ) * astr + k0 + lr    ];
                a[mt][1] = Abase[(mrow + lq + 8) * astr + k0 + lr    ];
                a[mt][2] = Abase[(mrow + lq    ) * astr + k0 + lr + 4];
                a[mt][3] = Abase[(mrow + lq + 8) * astr + k0 + lr + 4];
            }
            #pragma unroll
            for (int nt = 0; nt < 8; nt++) {
                int ncol = wn * 64 + nt * 8;
                uint32_t b0 = sB[(ncol + lq) * GSTR + k0 + lr    ];
                uint32_t b1 = sB[(ncol + lq) * GSTR + k0 + lr + 4];
                MMA_TF32(acc[0][nt], a[0], b0, b1);
                MMA_TF32(acc[1][nt], a[1], b0, b1);
            }
        }
        __syncthreads();
    }

    // ---- epilogue ----
    #pragma unroll
    for (int mt = 0; mt < 2; mt++) {
        int r_lo = row0 + wm * 32 + mt * 16 + lq;
        int r_hi = r_lo + 8;
        #pragma unroll
        for (int nt = 0; nt < 8; nt++) {
            int col = wn * 64 + nt * 8 + lr * 2;
            float bx = bias[col], by = bias[col + 1];
            float2 lo, hi;
            lo.x = acc[mt][nt][0] + bx; lo.y = acc[mt][nt][1] + by;
            hi.x = acc[mt][nt][2] + bx; hi.y = acc[mt][nt][3] + by;
            if (do_relu) {
                lo.x = fmaxf(lo.x, 0.f); lo.y = fmaxf(lo.y, 0.f);
                hi.x = fmaxf(hi.x, 0.f); hi.y = fmaxf(hi.y, 0.f);
            }
            if (r_lo < N_NODES) {
                *(float2*)(out + (size_t)r_lo * DF + col) = lo;
                if (do_relu)
                    *(__half2*)(hhout + (size_t)r_lo * DF + col) = __floats2half2_rn(lo.x, lo.y);
            }
            if (r_hi < N_NODES) {
                *(float2*)(out + (size_t)r_hi * DF + col) = hi;
                if (do_relu)
                    *(__half2*)(hhout + (size_t)r_hi * DF + col) = __floats2half2_rn(hi.x, hi.y);
            }
        }
    }
}

// ======================= pool (run-combining; also resets g_fill) ==========
#define POOL_NPT 8
__global__ void k_pool(const int* __restrict__ batch) {
    int idx = blockIdx.x * blockDim.x + threadIdx.x;
    if (idx < N_NODES) g_fill[idx] = 0;     // reset for next replay
    const int NGRP = N_NODES / POOL_NPT;    // 5000
    if (idx >= NGRP * 32) return;
    int grp = idx >> 5;
    int c = (idx & 31) * 4;
    int n0 = grp * POOL_NPT;
    int is64 = g_is64;

    int curg = -1;
    float4 m = make_float4(0.f, 0.f, 0.f, 0.f);
    #pragma unroll
    for (int i = 0; i < POOL_NPT; i++) {
        int node = n0 + i;
        int g = is64 ? batch[2 * node] : batch[node];
        float4 v = *(const float4*)(g_h0 + (size_t)node * DF + c);
        if (g != curg) {
            if (curg >= 0) {
                unsigned* o = &g_outmax[curg * DF + c];
                atomicMax(o + 0, enc_f(m.x));
                atomicMax(o + 1, enc_f(m.y));
                atomicMax(o + 2, enc_f(m.z));
                atomicMax(o + 3, enc_f(m.w));
            }
            curg = g; m = v;
        } else {
            m.x = fmaxf(m.x, v.x); m.y = fmaxf(m.y, v.y);
            m.z = fmaxf(m.z, v.z); m.w = fmaxf(m.w, v.w);
        }
    }
    unsigned* o = &g_outmax[curg * DF + c];
    atomicMax(o + 0, enc_f(m.x));
    atomicMax(o + 1, enc_f(m.y));
    atomicMax(o + 2, enc_f(m.z));
    atomicMax(o + 3, enc_f(m.w));
}

// decode + reset outmax to 0 (0 <= enc(f) for every float -> safe base)
__global__ void k_decode(float* __restrict__ out) {
    int i = blockIdx.x * blockDim.x + threadIdx.x;
    if (i < N_GRAPHS * DF) {
        out[i] = dec_f(g_outmax[i]);
        g_outmax[i] = 0u;
    }
}

// ===========================================================================
extern "C" void kernel_launch(void* const* d_in, const int* in_sizes, int n_in,
                              void* d_out, int out_size) {
    const float* x      = (const float*)d_in[0];
    const int*   edges  = (const int*)  d_in[1];   // int32 or int64 (probed)
    const int*   batch  = (const int*)  d_in[2];
    const float* Wrel0  = (const float*)d_in[3];
    const float* brel0  = (const float*)d_in[4];
    const float* Wroot0 = (const float*)d_in[5];
    const float* Wrel1  = (const float*)d_in[6];
    const float* brel1  = (const float*)d_in[7];
    const float* Wroot1 = (const float*)d_in[8];
    const float* Wrel2  = (const float*)d_in[9];
    const float* brel2  = (const float*)d_in[10];
    const float* Wroot2 = (const float*)d_in[11];
    float* out = (float*)d_out;

    static int s_attr_done = 0;
    if (!s_attr_done) {
        cudaFuncSetAttribute(k_layer, cudaFuncAttributeMaxDynamicSharedMemorySize,
                             SM_WORDS * 4);
        s_attr_done = 1;
    }

    k_init<<<N_NODES * DF / 2 / 256, 256>>>(edges, x, Wrel0, Wroot0, Wrel1, Wroot1, Wrel2, Wroot2);
    k_scan_part<<<SCAN_BLK, 256>>>();
    k_scan_top<<<1, 256>>>();
    k_scan_wr<<<SCAN_BLK, 256>>>();
    k_fill<<<N_EDGES / 256, 256>>>(edges);

    const int LAYER_BLOCKS = (N_NODES + 127) / 128;  // 313
    // layer 0: gather(hhA=x16) + gemm(root=x)  -> h0 (ReLU), hhB
    k_layer<<<LAYER_BLOCKS, 256, SM_WORDS * 4>>>(x, 0, 0, 0, brel0, 1, 0);
    // layer 1: gather(hhB) + gemm(root=h0)     -> h1 (ReLU), hhA
    k_layer<<<LAYER_BLOCKS, 256, SM_WORDS * 4>>>(x, 1, 1, 1, brel1, 1, 1);
    // layer 2: gather(hhA) + gemm(root=h1)     -> h0 (no ReLU)
    k_layer<<<LAYER_BLOCKS, 256, SM_WORDS * 4>>>(x, 2, 0, 2, brel2, 0, 0);

    k_pool<<<(N_NODES / POOL_NPT * 32 + 255) / 256, 256>>>(batch);
    k_decode<<<(N_GRAPHS * DF + 255) / 256, 256>>>(out);
}

// round 14
// speedup vs baseline: 1.2556x; 1.2556x over previous
#include <cuda_runtime.h>
#include <cuda_fp16.h>
#include <cstdint>

#define N_NODES 40000
#define N_EDGES 640000
#define DF      128
#define N_GRAPHS 128

// ======================= scratch (static device globals) ====================
// Replay invariants (statics zero-init at load; resets by last reader):
//   g_deg    : zeroed inside k_scan after read
//   g_fill   : zeroed by k_pool
//   g_outmax : reset to 0 by k_decode (0 <= enc(f) for all f)
//   g_sstate : reset to 0 by k_decode
__device__ float  g_agg[(size_t)N_NODES * DF];
__device__ float  g_h0 [(size_t)N_NODES * DF];
__device__ float  g_h1 [(size_t)N_NODES * DF];
__device__ __half g_hhA[(size_t)N_NODES * DF];   // fp16 mirrors (double buffer)
__device__ __half g_hhB[(size_t)N_NODES * DF];
__device__ float  g_WT [3][DF][256];             // [layer][n][k_cat]
__device__ int    g_rowptr[N_NODES + 1];
__device__ int    g_deg [N_NODES];
__device__ int    g_fill[N_NODES];
__device__ int    g_colidx[N_EDGES];
__device__ unsigned g_sstate[160];               // decoupled-lookback state (UNSIGNED)
__device__ unsigned g_outmax[N_GRAPHS * DF];
__device__ int    g_is64;

// ======================= helpers ===========================================
__device__ __forceinline__ uint32_t f2tf32(float f) {
    uint32_t r;
    asm("cvt.rna.tf32.f32 %0, %1;" : "=r"(r) : "f"(f));
    return r;
}

#define MMA_TF32(d, a, b0, b1)                                                \
    asm volatile("mma.sync.aligned.m16n8k8.row.col.f32.tf32.tf32.f32 "        \
        "{%0,%1,%2,%3}, {%4,%5,%6,%7}, {%8,%9}, {%0,%1,%2,%3};"               \
        : "+f"((d)[0]), "+f"((d)[1]), "+f"((d)[2]), "+f"((d)[3])              \
        : "r"((a)[0]), "r"((a)[1]), "r"((a)[2]), "r"((a)[3]),                 \
          "r"(b0), "r"(b1))

__device__ __forceinline__ unsigned enc_f(float f) {
    unsigned b = __float_as_uint(f);
    return (b & 0x80000000u) ? ~b : (b | 0x80000000u);
}
__device__ __forceinline__ float dec_f(unsigned u) {
    unsigned b = (u & 0x80000000u) ? (u ^ 0x80000000u) : ~u;
    return __uint_as_float(b);
}

// ======================= init: x->fp16, WT transpose, probe+count ==========
// Grid 10000x256. g_deg is pre-zeroed (static init / previous replay's scan).
__global__ void k_init(const int* __restrict__ ew, const float* __restrict__ x,
                       const float* __restrict__ Wrel0, const float* __restrict__ Wroot0,
                       const float* __restrict__ Wrel1, const float* __restrict__ Wroot1,
                       const float* __restrict__ Wrel2, const float* __restrict__ Wroot2) {
    __shared__ int s_any;
    int i = blockIdx.x * blockDim.x + threadIdx.x;

    // x -> half mirror A (exactly 2.56M half2)
    {
        float2 v = *((const float2*)x + i);
        *((__half2*)g_hhA + i) = __floats2half2_rn(v.x, v.y);
    }

    // weight transpose: 3 * 128 * 256 elements
    if (i < 3 * DF * 256) {
        int layer = i / (DF * 256);
        int idx = i % (DF * 256);
        const float* Wrel  = (layer == 0) ? Wrel0  : (layer == 1) ? Wrel1  : Wrel2;
        const float* Wroot = (layer == 0) ? Wroot0 : (layer == 1) ? Wroot1 : Wroot2;
        int n = idx >> 8;
        int k = idx & 255;
        g_WT[layer][n][k] = (k < DF) ? Wrel[k * DF + n] : Wroot[(k - DF) * DF + n];
    }

    // blocks covering the edge range: block-local probe, then count
    if (blockIdx.x * 256 < N_EDGES) {
        if (threadIdx.x == 0) s_any = 0;
        __syncthreads();
        if (ew[2 * threadIdx.x + 1] != 0) atomicOr(&s_any, 1);
        __syncthreads();
        int is64 = s_any ? 0 : 1;
        if (i == 0) g_is64 = is64;
        if (i < N_EDGES) {
            int dst = is64 ? ew[2 * (N_EDGES + i)] : ew[N_EDGES + i];
            atomicAdd(&g_deg[dst], 1);
        }
    }
}

// ======================= single-pass scan (decoupled lookback) =============
// 157 blocks (all co-resident -> lookback terminates). UNSIGNED state word:
// bits[30:32) status (1=aggregate, 2=inclusive prefix), bits[0:30) value.
#define SCAN_BLK 157

__global__ void k_scan() {
    __shared__ int sh[256];
    __shared__ int s_prefix;
    int t = threadIdx.x;
    int b = blockIdx.x;
    int i = b * 256 + t;
    int v = (i < N_NODES) ? g_deg[i] : 0;

    sh[t] = v;
    __syncthreads();
    for (int off = 1; off < 256; off <<= 1) {
        int x = (t >= off) ? sh[t - off] : 0;
        __syncthreads();
        sh[t] += x;
        __syncthreads();
    }
    unsigned total = (unsigned)sh[255];

    if (t == 0) {
        if (b == 0) {
            s_prefix = 0;
            atomicExch(&g_sstate[0], (2u << 30) | total);
        } else {
            atomicExch(&g_sstate[b], (1u << 30) | total);
            unsigned pfx = 0;
            int j = b - 1;
            while (1) {
                unsigned s = atomicAdd(&g_sstate[j], 0u);
                unsigned st = s >> 30;
                if (st == 2u) { pfx += s & 0x3FFFFFFFu; break; }
                if (st == 1u) { pfx += s & 0x3FFFFFFFu; j--; }
            }
            atomicExch(&g_sstate[b], (2u << 30) | (pfx + total));
            s_prefix = (int)pfx;
        }
    }
    __syncthreads();

    if (i < N_NODES) {
        g_rowptr[i] = s_prefix + sh[t] - v;   // exclusive
        g_deg[i] = 0;                          // reset for next replay
    }
    if (b == 0 && t == 0) g_rowptr[N_NODES] = N_EDGES;
}

__global__ void k_fill(const int* __restrict__ ew) {
    int e = blockIdx.x * blockDim.x + threadIdx.x;
    if (e >= N_EDGES) return;
    int is64 = g_is64;
    int src = is64 ? ew[2 * e] : ew[e];
    int dst = is64 ? ew[2 * (N_EDGES + e)] : ew[N_EDGES + e];
    int pos = atomicAdd(&g_fill[dst], 1);
    g_colidx[g_rowptr[dst] + pos] = src;
}

// ======================= edge aggregation (fp16 gather, 1 warp/node) =======
__global__ void __launch_bounds__(256) k_agg(int hh_rd) {
    const __half* hhin = hh_rd ? g_hhB : g_hhA;
    int gwarp = (blockIdx.x * blockDim.x + threadIdx.x) >> 5;
    int lane = threadIdx.x & 31;
    if (gwarp >= N_NODES) return;
    int beg = g_rowptr[gwarp];
    int end = g_rowptr[gwarp + 1];
    float4 acc = make_float4(0.f, 0.f, 0.f, 0.f);
    int e = beg;
    for (; e + 3 < end; e += 4) {
        int s0 = g_colidx[e + 0];
        int s1 = g_colidx[e + 1];
        int s2 = g_colidx[e + 2];
        int s3 = g_colidx[e + 3];
        uint2 u0 = __ldg((const uint2*)(hhin + (size_t)s0 * DF) + lane);
        uint2 u1 = __ldg((const uint2*)(hhin + (size_t)s1 * DF) + lane);
        uint2 u2 = __ldg((const uint2*)(hhin + (size_t)s2 * DF) + lane);
        uint2 u3 = __ldg((const uint2*)(hhin + (size_t)s3 * DF) + lane);
        float2 a0 = __half22float2(*(__half2*)&u0.x), b0 = __half22float2(*(__half2*)&u0.y);
        float2 a1 = __half22float2(*(__half2*)&u1.x), b1 = __half22float2(*(__half2*)&u1.y);
        float2 a2 = __half22float2(*(__half2*)&u2.x), b2 = __half22float2(*(__half2*)&u2.y);
        float2 a3 = __half22float2(*(__half2*)&u3.x), b3 = __half22float2(*(__half2*)&u3.y);
        acc.x += (a0.x + a1.x) + (a2.x + a3.x);
        acc.y += (a0.y + a1.y) + (a2.y + a3.y);
        acc.z += (b0.x + b1.x) + (b2.x + b3.x);
        acc.w += (b0.y + b1.y) + (b2.y + b3.y);
    }
    for (; e < end; e++) {
        int s0 = g_colidx[e];
        uint2 u0 = __ldg((const uint2*)(hhin + (size_t)s0 * DF) + lane);
        float2 a0 = __half22float2(*(__half2*)&u0.x), b0 = __half22float2(*(__half2*)&u0.y);
        acc.x += a0.x; acc.y += a0.y; acc.z += b0.x; acc.w += b0.y;
    }
    *((float4*)(g_agg + (size_t)gwarp * DF) + lane) = acc;
}

// ======================= tf32 mma.sync GEMM ================================
// Per CTA: 128 rows out = [g_agg | root] (K=256) @ WT^T (N=128), + bias, ReLU.
// When do_relu, also writes the fp16 mirror for the next layer's gather.
#define GSTR 36

__global__ void __launch_bounds__(256) k_gemm_mma(
    const float* __restrict__ xext, int root_sel, int out_sel, int layer,
    const float* __restrict__ bias, int do_relu, int hh_wr)
{
    __shared__ uint32_t sA[128 * GSTR];   // [m][k] tf32 bits
    __shared__ uint32_t sB[128 * GSTR];   // [n][k] tf32 bits

    const float* Aroot = (root_sel == 0) ? xext : (root_sel == 1 ? g_h0 : g_h1);
    float* out = (out_sel == 0) ? g_h0 : g_h1;
    __half* hhout = hh_wr ? g_hhB : g_hhA;

    int tid = threadIdx.x;
    int wid = tid >> 5;
    int lane = tid & 31;
    int row0 = blockIdx.x * 128;
    int wm = wid & 3;
    int wn = wid >> 2;
    int lq = lane >> 2;
    int lr = lane & 3;

    const float* Bsrc = &g_WT[layer][0][0];

    float acc[2][8][4];
    #pragma unroll
    for (int mt = 0; mt < 2; mt++)
        #pragma unroll
        for (int nt = 0; nt < 8; nt++)
            #pragma unroll
            for (int q = 0; q < 4; q++) acc[mt][nt][q] = 0.f;

    for (int c = 0; c < 8; c++) {
        int kbase = c * 32;
        const float* Asrc = (kbase < 128) ? g_agg : Aroot;
        int acol = kbase & 127;

        #pragma unroll
        for (int it = 0; it < 4; it++) {
            int idx = it * 256 + tid;
            int r = idx >> 3, c4 = idx & 7;
            int grow = row0 + r;
            float4 v = make_float4(0.f, 0.f, 0.f, 0.f);
            if (grow < N_NODES)
                v = *(const float4*)(Asrc + (size_t)grow * DF + acol + c4 * 4);
            uint4 p;
            p.x = f2tf32(v.x); p.y = f2tf32(v.y);
            p.z = f2tf32(v.z); p.w = f2tf32(v.w);
            *(uint4*)&sA[r * GSTR + c4 * 4] = p;
        }
        #pragma unroll
        for (int it = 0; it < 4; it++) {
            int idx = it * 256 + tid;
            int n = idx >> 3, c4 = idx & 7;
            float4 v = *(const float4*)(Bsrc + (size_t)n * 256 + kbase + c4 * 4);
            uint4 p;
            p.x = f2tf32(v.x); p.y = f2tf32(v.y);
            p.z = f2tf32(v.z); p.w = f2tf32(v.w);
            *(uint4*)&sB[n * GSTR + c4 * 4] = p;
        }
        __syncthreads();

        #pragma unroll
        for (int ks = 0; ks < 4; ks++) {
            int k0 = ks * 8;
            uint32_t a[2][4];
            #pragma unroll
            for (int mt = 0; mt < 2; mt++) {
                int mrow = wm * 32 + mt * 16;
                a[mt][0] = sA[(mrow + lq    ) * GSTR + k0 + lr    ];
                a[mt][1] = sA[(mrow + lq + 8) * GSTR + k0 + lr    ];
                a[mt][2] = sA[(mrow + lq    ) * GSTR + k0 + lr + 4];
                a[mt][3] = sA[(mrow + lq + 8) * GSTR + k0 + lr + 4];
            }
            #pragma unroll
            for (int nt = 0; nt < 8; nt++) {
                int ncol = wn * 64 + nt * 8;
                uint32_t b0 = sB[(ncol + lq) * GSTR + k0 + lr    ];
                uint32_t b1 = sB[(ncol + lq) * GSTR + k0 + lr + 4];
                MMA_TF32(acc[0][nt], a[0], b0, b1);
                MMA_TF32(acc[1][nt], a[1], b0, b1);
            }
        }
        __syncthreads();
    }

    #pragma unroll
    for (int mt = 0; mt < 2; mt++) {
        int r_lo = row0 + wm * 32 + mt * 16 + lq;
        int r_hi = r_lo + 8;
        #pragma unroll
        for (int nt = 0; nt < 8; nt++) {
            int col = wn * 64 + nt * 8 + lr * 2;
            float bx = bias[col], by = bias[col + 1];
            float2 lo, hi;
            lo.x = acc[mt][nt][0] + bx; lo.y = acc[mt][nt][1] + by;
            hi.x = acc[mt][nt][2] + bx; hi.y = acc[mt][nt][3] + by;
            if (do_relu) {
                lo.x = fmaxf(lo.x, 0.f); lo.y = fmaxf(lo.y, 0.f);
                hi.x = fmaxf(hi.x, 0.f); hi.y = fmaxf(hi.y, 0.f);
            }
            if (r_lo < N_NODES) {
                *(float2*)(out + (size_t)r_lo * DF + col) = lo;
                if (do_relu)
                    *(__half2*)(hhout + (size_t)r_lo * DF + col) = __floats2half2_rn(lo.x, lo.y);
            }
            if (r_hi < N_NODES) {
                *(float2*)(out + (size_t)r_hi * DF + col) = hi;
                if (do_relu)
                    *(__half2*)(hhout + (size_t)r_hi * DF + col) = __floats2half2_rn(hi.x, hi.y);
            }
        }
    }
}

// ======================= pool (run-combining; also resets g_fill) ==========
#define POOL_NPT 8
__global__ void k_pool(const int* __restrict__ batch) {
    int idx = blockIdx.x * blockDim.x + threadIdx.x;
    if (idx < N_NODES) g_fill[idx] = 0;
    const int NGRP = N_NODES / POOL_NPT;    // 5000
    if (idx >= NGRP * 32) return;
    int grp = idx >> 5;
    int c = (idx & 31) * 4;
    int n0 = grp * POOL_NPT;
    int is64 = g_is64;

    int curg = -1;
    float4 m = make_float4(0.f, 0.f, 0.f, 0.f);
    #pragma unroll
    for (int i = 0; i < POOL_NPT; i++) {
        int node = n0 + i;
        int g = is64 ? batch[2 * node] : batch[node];
        float4 v = *(const float4*)(g_h0 + (size_t)node * DF + c);
        if (g != curg) {
            if (curg >= 0) {
                unsigned* o = &g_outmax[curg * DF + c];
                atomicMax(o + 0, enc_f(m.x));
                atomicMax(o + 1, enc_f(m.y));
                atomicMax(o + 2, enc_f(m.z));
                atomicMax(o + 3, enc_f(m.w));
            }
            curg = g; m = v;
        } else {
            m.x = fmaxf(m.x, v.x); m.y = fmaxf(m.y, v.y);
            m.z = fmaxf(m.z, v.z); m.w = fmaxf(m.w, v.w);
        }
    }
    unsigned* o = &g_outmax[curg * DF + c];
    atomicMax(o + 0, enc_f(m.x));
    atomicMax(o + 1, enc_f(m.y));
    atomicMax(o + 2, enc_f(m.z));
    atomicMax(o + 3, enc_f(m.w));
}

// decode + reset outmax and scan state for next replay
__global__ void k_decode(float* __restrict__ out) {
    int i = blockIdx.x * blockDim.x + threadIdx.x;
    if (i < N_GRAPHS * DF) {
        out[i] = dec_f(g_outmax[i]);
        g_outmax[i] = 0u;
    }
    if (i < SCAN_BLK) g_sstate[i] = 0u;
}

// ===========================================================================
extern "C" void kernel_launch(void* const* d_in, const int* in_sizes, int n_in,
                              void* d_out, int out_size) {
    const float* x      = (const float*)d_in[0];
    const int*   edges  = (const int*)  d_in[1];   // int32 or int64 (probed)
    const int*   batch  = (const int*)  d_in[2];
    const float* Wrel0  = (const float*)d_in[3];
    const float* brel0  = (const float*)d_in[4];
    const float* Wroot0 = (const float*)d_in[5];
    const float* Wrel1  = (const float*)d_in[6];
    const float* brel1  = (const float*)d_in[7];
    const float* Wroot1 = (const float*)d_in[8];
    const float* Wrel2  = (const float*)d_in[9];
    const float* brel2  = (const float*)d_in[10];
    const float* Wroot2 = (const float*)d_in[11];
    float* out = (float*)d_out;

    k_init<<<N_NODES * DF / 2 / 256, 256>>>(edges, x, Wrel0, Wroot0, Wrel1, Wroot1, Wrel2, Wroot2);
    k_scan<<<SCAN_BLK, 256>>>();
    k_fill<<<N_EDGES / 256, 256>>>(edges);

    const int AGG_BLOCKS = N_NODES / 8;            // 8 warps/block, 1 node/warp
    const int GEMM_BLOCKS = (N_NODES + 127) / 128; // 313

    // layer 0: agg(hhA=x16) -> gemm([agg|x]) -> h0 (ReLU) + hhB
    k_agg<<<AGG_BLOCKS, 256>>>(0);
    k_gemm_mma<<<GEMM_BLOCKS, 256>>>(x, 0, 0, 0, brel0, 1, 1);
    // layer 1: agg(hhB) -> gemm([agg|h0]) -> h1 (ReLU) + hhA
    k_agg<<<AGG_BLOCKS, 256>>>(1);
    k_gemm_mma<<<GEMM_BLOCKS, 256>>>(x, 1, 1, 1, brel1, 1, 0);
    // layer 2: agg(hhA) -> gemm([agg|h1]) -> h0 (no ReLU)
    k_agg<<<AGG_BLOCKS, 256>>>(0);
    k_gemm_mma<<<GEMM_BLOCKS, 256>>>(x, 2, 0, 2, brel2, 0, 0);

    k_pool<<<(N_NODES / POOL_NPT * 32 + 255) / 256, 256>>>(batch);
    k_decode<<<(N_GRAPHS * DF + 255) / 256, 256>>>(out);
}